// round 13
// baseline (speedup 1.0000x reference)
#include <cuda_runtime.h>
#include <cstdint>

// Identity op: reference output == input X (the torch module's loop writes
// are dead code; output is exactly the input tensor). Pure 128 MiB HBM copy.
//
// CONVERGED. Session evidence (8 benched variants): mixed read+write DRAM
// ceiling is ~7.1-7.3 TB/s effective on this part; all reasonable copy
// kernels land within ~1us run-to-run noise of it. Falsified levers: cache
// operators (.cg/.cs), L2 eviction priorities, driver memcpy node, exact-fit
// predicate elision (regressed via occupancy-induced L1tex contention),
// 512-thread blocks. TMA ruled out analytically (LTS cap path-independent).
//
// Final config (best 2-of-3 kernel times 36.7/36.9/37.6us, best wall
// 44.9us): 256-thread blocks, 4 x 256-bit v8.f32 per thread, loads
// front-batched, bounds-predicated (regs ~44 -> occ ~49%, the empirically
// best occupancy point for this streaming pattern).

__device__ __forceinline__ void ldg256(const float* __restrict__ p, float* v) {
    asm volatile(
        "ld.global.nc.v8.f32 {%0,%1,%2,%3,%4,%5,%6,%7}, [%8];"
        : "=f"(v[0]), "=f"(v[1]), "=f"(v[2]), "=f"(v[3]),
          "=f"(v[4]), "=f"(v[5]), "=f"(v[6]), "=f"(v[7])
        : "l"(p));
}

__device__ __forceinline__ void stg256(float* __restrict__ p, const float* v) {
    asm volatile(
        "st.global.v8.f32 [%0], {%1,%2,%3,%4,%5,%6,%7,%8};"
        :: "l"(p),
           "f"(v[0]), "f"(v[1]), "f"(v[2]), "f"(v[3]),
           "f"(v[4]), "f"(v[5]), "f"(v[6]), "f"(v[7])
        : "memory");
}

constexpr int V8PT = 4;      // 4 x 32 B = 128 B per thread
constexpr int THREADS = 256;

__global__ void __launch_bounds__(THREADS)
copy_v8_kernel(const float* __restrict__ src,
               float* __restrict__ dst,
               long long n8) {   // count of float8 chunks
    long long base = (long long)blockIdx.x * (THREADS * V8PT) + threadIdx.x;

    float v[V8PT][8];
    // Front-batch all loads: 4 independent 256-bit LDGs in flight per thread.
    #pragma unroll
    for (int j = 0; j < V8PT; j++) {
        long long i = base + (long long)j * THREADS;
        if (i < n8) ldg256(src + i * 8, v[j]);
    }
    #pragma unroll
    for (int j = 0; j < V8PT; j++) {
        long long i = base + (long long)j * THREADS;
        if (i < n8) stg256(dst + i * 8, v[j]);
    }
}

// Scalar fallback for arbitrary sizes/alignment (not expected: n = 2^25,
// buffers 256B-aligned by the allocator).
__global__ void copy_f1_kernel(const float* __restrict__ src,
                               float* __restrict__ dst,
                               long long n) {
    long long i = (long long)blockIdx.x * blockDim.x + threadIdx.x;
    long long stride = (long long)gridDim.x * blockDim.x;
    for (; i < n; i += stride) dst[i] = src[i];
}

extern "C" void kernel_launch(void* const* d_in, const int* in_sizes, int n_in,
                              void* d_out, int out_size) {
    const float* x = (const float*)d_in[0];
    float* out = (float*)d_out;
    long long n = (long long)out_size;   // 33,554,432 floats expected

    if ((n & 7) == 0 && (((uintptr_t)x | (uintptr_t)out) & 31) == 0) {
        long long n8 = n >> 3;
        const long long per_block = (long long)THREADS * V8PT;   // 1024 float8
        long long blocks_ll = (n8 + per_block - 1) / per_block;  // 4096 expected
        if (blocks_ll <= 1048576LL) {
            copy_v8_kernel<<<(int)blocks_ll, THREADS>>>(x, out, n8);
            return;
        }
    }
    int blocks = (int)(((n >> 2) + 255) / 256);
    if (blocks < 1) blocks = 1;
    if (blocks > 262144) blocks = 262144;
    copy_f1_kernel<<<blocks, 256>>>(x, out, n);
}